// round 3
// baseline (speedup 1.0000x reference)
#include <cuda_runtime.h>

#define NV 4096            // nodes per graph
#define NB 32              // batch size (== warp size, load-bearing)
#define BN (NV * NB)       // 131072
#define CAP 256            // ELL row capacity (mean degree 128, +11 sigma headroom)

// ---- scratch (device globals; zero-initialized at load, counters kept zero
//      across calls by re-zeroing in the final kernel) ----
__device__ float  g_xt  [BN];        // x,  node-major [node][batch]
__device__ float  g_fxt [BN];        // tanh(x), node-major
__device__ float  g_mut [BN];        // mu, node-major
__device__ float  g_epst[BN];        // eps = x - mu, node-major
__device__ float  g_dxt [BN];        // dx, node-major
__device__ int    g_cnt_dst[NV];
__device__ int    g_cnt_src[NV];
__device__ float2 g_ellF[NV * CAP];  // rows keyed by dst: (src, w)
__device__ float2 g_ellB[NV * CAP];  // rows keyed by src: (dst, w)

// ============================================================================
// Fused prep (transpose + tanh) + ELL build. 256 threads/block.
// blocks [0,128)   : transpose x [B,N] -> node-major, tanh
// blocks [128,640) : build both ELL structures, 4 edges/thread (ILP for ATOMG)
// Counters are guaranteed zero at kernel entry (BSS init / k_fin re-zero).
// ============================================================================
__global__ void k_pb(const float* __restrict__ x,
                     const float* __restrict__ w,
                     const int*   __restrict__ esrc,
                     const int*   __restrict__ edst, int E) {
    if (blockIdx.x < 128) {
        __shared__ float s[32][33];
        int tx  = threadIdx.x & 31;
        int ty0 = threadIdx.x >> 5;          // 0..7
        int i0  = blockIdx.x * 32;
        #pragma unroll
        for (int r = 0; r < 4; r++) {
            int ty = ty0 + (r << 3);
            s[ty][tx] = x[ty * NV + i0 + tx];            // batch-major read
        }
        __syncthreads();
        #pragma unroll
        for (int r = 0; r < 4; r++) {
            int ty = ty0 + (r << 3);
            float xv = s[tx][ty];
            int o = (i0 + ty) * NB + tx;                 // node-major write
            g_xt[o]  = xv;
            g_fxt[o] = tanhf(xv);
        }
        return;
    }
    // ---- build ----
    int t  = (blockIdx.x - 128) * 256 + threadIdx.x;
    int e0 = t << 2;
    if (e0 + 3 >= E && e0 >= E) return;
    if (e0 + 4 <= E) {
        int4   s4 = *(const int4*)  (esrc + e0);
        int4   d4 = *(const int4*)  (edst + e0);
        float4 w4 = *(const float4*)(w    + e0);
        int p0 = atomicAdd(&g_cnt_dst[d4.x], 1);
        int p1 = atomicAdd(&g_cnt_dst[d4.y], 1);
        int p2 = atomicAdd(&g_cnt_dst[d4.z], 1);
        int p3 = atomicAdd(&g_cnt_dst[d4.w], 1);
        int q0 = atomicAdd(&g_cnt_src[s4.x], 1);
        int q1 = atomicAdd(&g_cnt_src[s4.y], 1);
        int q2 = atomicAdd(&g_cnt_src[s4.z], 1);
        int q3 = atomicAdd(&g_cnt_src[s4.w], 1);
        if (p0 < CAP) g_ellF[(d4.x << 8) + p0] = make_float2(__int_as_float(s4.x), w4.x);
        if (p1 < CAP) g_ellF[(d4.y << 8) + p1] = make_float2(__int_as_float(s4.y), w4.y);
        if (p2 < CAP) g_ellF[(d4.z << 8) + p2] = make_float2(__int_as_float(s4.z), w4.z);
        if (p3 < CAP) g_ellF[(d4.w << 8) + p3] = make_float2(__int_as_float(s4.w), w4.w);
        if (q0 < CAP) g_ellB[(s4.x << 8) + q0] = make_float2(__int_as_float(d4.x), w4.x);
        if (q1 < CAP) g_ellB[(s4.y << 8) + q1] = make_float2(__int_as_float(d4.y), w4.y);
        if (q2 < CAP) g_ellB[(s4.z << 8) + q2] = make_float2(__int_as_float(d4.z), w4.z);
        if (q3 < CAP) g_ellB[(s4.w << 8) + q3] = make_float2(__int_as_float(d4.w), w4.w);
    } else {
        for (int e = e0; e < E; e++) {
            int s = esrc[e], d = edst[e];
            float wt = w[e];
            int p = atomicAdd(&g_cnt_dst[d], 1);
            if (p < CAP) g_ellF[(d << 8) + p] = make_float2(__int_as_float(s), wt);
            int q = atomicAdd(&g_cnt_src[s], 1);
            if (q < CAP) g_ellB[(s << 8) + q] = make_float2(__int_as_float(d), wt);
        }
    }
}

// ============================================================================
// Half-warp float2 SpMM slice. lane covers batches (2*(lane&15), +1);
// half-warp 0 takes even edges of a pair, half-warp 1 odd. One LDG per edge.
// Returns (sx, sy) fully reduced across the two half-warps.
// ============================================================================
__device__ __forceinline__ float2 spmm_hw(const float2* __restrict__ row,
                                          const float* __restrict__ tab,
                                          int pb, int pe, int n, int q,
                                          int half, int off) {
    float ax0=0.f, ay0=0.f, ax1=0.f, ay1=0.f;
    float ax2=0.f, ay2=0.f, ax3=0.f, ay3=0.f;
    int p = pb;
    for (; p + 4 <= pe; p += 4) {
        float2 e0 = row[((p + 0) << 1) + half];
        float2 e1 = row[((p + 1) << 1) + half];
        float2 e2 = row[((p + 2) << 1) + half];
        float2 e3 = row[((p + 3) << 1) + half];
        float2 v0 = *(const float2*)(tab + (__float_as_int(e0.x) << 5) + off);
        float2 v1 = *(const float2*)(tab + (__float_as_int(e1.x) << 5) + off);
        float2 v2 = *(const float2*)(tab + (__float_as_int(e2.x) << 5) + off);
        float2 v3 = *(const float2*)(tab + (__float_as_int(e3.x) << 5) + off);
        ax0 = fmaf(e0.y, v0.x, ax0); ay0 = fmaf(e0.y, v0.y, ay0);
        ax1 = fmaf(e1.y, v1.x, ax1); ay1 = fmaf(e1.y, v1.y, ay1);
        ax2 = fmaf(e2.y, v2.x, ax2); ay2 = fmaf(e2.y, v2.y, ay2);
        ax3 = fmaf(e3.y, v3.x, ax3); ay3 = fmaf(e3.y, v3.y, ay3);
    }
    for (; p < pe; p++) {
        float2 e0 = row[(p << 1) + half];
        float2 v0 = *(const float2*)(tab + (__float_as_int(e0.x) << 5) + off);
        ax0 = fmaf(e0.y, v0.x, ax0); ay0 = fmaf(e0.y, v0.y, ay0);
    }
    // odd leftover edge (only warp q==3, only half 0, counted once)
    if (q == 3 && (n & 1) && half == 0) {
        float2 e0 = row[n - 1];
        float2 v0 = *(const float2*)(tab + (__float_as_int(e0.x) << 5) + off);
        ax0 = fmaf(e0.y, v0.x, ax0); ay0 = fmaf(e0.y, v0.y, ay0);
    }
    float sx = (ax0 + ax1) + (ax2 + ax3);
    float sy = (ay0 + ay1) + (ay2 + ay3);
    sx += __shfl_xor_sync(0xffffffffu, sx, 16);
    sy += __shfl_xor_sync(0xffffffffu, sy, 16);
    return make_float2(sx, sy);
}

// Forward SpMM: mu = sum w * fx[src]; eps = x - mu. 4 warps/node, 2 nodes/CTA.
__global__ void k_mu() {
    __shared__ float part[2][4][32];
    int warp  = threadIdx.x >> 5;
    int lane  = threadIdx.x & 31;
    int local = warp >> 2;
    int q     = warp & 3;
    int node  = (blockIdx.x << 1) + local;

    int n     = min(g_cnt_dst[node], CAP);
    int npair = n >> 1;
    int pb    = (npair * q) >> 2;
    int pe    = (npair * (q + 1)) >> 2;
    int half  = lane >> 4;
    int off   = (lane & 15) << 1;

    float2 s2 = spmm_hw(g_ellF + (node << 8), g_fxt, pb, pe, n, q, half, off);
    if (lane < 16) {
        part[local][q][off]     = s2.x;
        part[local][q][off + 1] = s2.y;
    }
    __syncthreads();
    if (q == 0) {
        float mu = (part[local][0][lane] + part[local][1][lane])
                 + (part[local][2][lane] + part[local][3][lane]);
        int o = (node << 5) + lane;
        g_mut[o]  = mu;
        g_epst[o] = g_xt[o] - mu;
    }
}

// Backward SpMM + fused mu-output transpose.
// blocks [0,2048): dx = -eps + (1-fx^2) * sum w * eps[dst]
// blocks [2048,2176): transpose g_mut -> out[0, B*N] (g_mut ready after k_mu)
__global__ void k_dx(float* __restrict__ out) {
    __shared__ float sh[2][4][33];   // 264 floats; reused as 32x33 tile below
    if (blockIdx.x < 2048) {
        int warp  = threadIdx.x >> 5;
        int lane  = threadIdx.x & 31;
        int local = warp >> 2;
        int q     = warp & 3;
        int node  = (blockIdx.x << 1) + local;

        int n     = min(g_cnt_src[node], CAP);
        int npair = n >> 1;
        int pb    = (npair * q) >> 2;
        int pe    = (npair * (q + 1)) >> 2;
        int half  = lane >> 4;
        int off   = (lane & 15) << 1;

        float2 s2 = spmm_hw(g_ellB + (node << 8), g_epst, pb, pe, n, q, half, off);
        if (lane < 16) {
            sh[local][q][off]     = s2.x;
            sh[local][q][off + 1] = s2.y;
        }
        __syncthreads();
        if (q == 0) {
            float acc = (sh[local][0][lane] + sh[local][1][lane])
                      + (sh[local][2][lane] + sh[local][3][lane]);
            int o = (node << 5) + lane;
            float eps = g_epst[o];
            float fx  = g_fxt[o];
            g_dxt[o] = fmaf(fmaf(-fx, fx, 1.0f), acc, -eps);
        }
        return;
    }
    // ---- mu output transpose (node-major -> batch-major) ----
    __shared__ float s[32][33];
    int b   = blockIdx.x - 2048;       // 0..127
    int t0  = b * 32;
    int tx  = threadIdx.x & 31;
    int ty0 = threadIdx.x >> 5;        // 0..7
    #pragma unroll
    for (int r = 0; r < 4; r++) {
        int ty = ty0 + (r << 3);
        s[ty][tx] = g_mut[(t0 + ty) * NB + tx];
    }
    __syncthreads();
    #pragma unroll
    for (int r = 0; r < 4; r++) {
        int ty = ty0 + (r << 3);
        out[ty * NV + t0 + tx] = s[tx][ty];
    }
}

// Final: transpose dx -> out[1, B*N]; re-zero counters (invariant for next call).
__global__ void k_fin(float* __restrict__ out) {
    __shared__ float s[32][33];
    int t0  = blockIdx.x * 32;
    int tx  = threadIdx.x & 31;
    int ty0 = threadIdx.x >> 5;
    #pragma unroll
    for (int r = 0; r < 4; r++) {
        int ty = ty0 + (r << 3);
        s[ty][tx] = g_dxt[(t0 + ty) * NB + tx];
    }
    __syncthreads();
    #pragma unroll
    for (int r = 0; r < 4; r++) {
        int ty = ty0 + (r << 3);
        out[BN + ty * NV + t0 + tx] = s[tx][ty];
    }
    int gid = blockIdx.x * 256 + threadIdx.x;   // 32768 threads, need 4096
    if (gid < NV) { g_cnt_dst[gid] = 0; g_cnt_src[gid] = 0; }
}

extern "C" void kernel_launch(void* const* d_in, const int* in_sizes, int n_in,
                              void* d_out, int out_size) {
    const float* x    = (const float*)d_in[0];
    const float* w    = (const float*)d_in[1];
    const int*   esrc = (const int*)d_in[2];
    const int*   edst = (const int*)d_in[3];
    float*       out  = (float*)d_out;
    int E = in_sizes[1];

    k_pb <<<128 + (E + 1023) / 1024, 256>>>(x, w, esrc, edst, E);
    k_mu <<<NV / 2, 256>>>();
    k_dx <<<NV / 2 + 128, 256>>>(out);
    k_fin<<<128, 256>>>(out);
}